// round 1
// baseline (speedup 1.0000x reference)
#include <cuda_runtime.h>
#include <float.h>

// Problem constants (fixed shapes per reference)
#define B_DIM 4
#define H_DIM 16
#define L_DIM 2048
#define D_DIM 64
#define TOPK  128
#define SCALE 0.125f      // D^-0.5 = 1/8

#define BQ 16             // queries per CTA
#define BK 256            // key tile
#define NTHREADS 256
#define LIST_CAP 256
#define KSTR 68           // padded row stride in floats (17 float4) -> conflict-free
#define KSTR4 17

// smem layout (floats):
//   S      : [BQ][2048]      = 32768
//   Ks     : [BK][KSTR]      = 17408
//   Qs     : [BQ][KSTR]      = 1088
//   klist  : [8][LIST_CAP]   = 2048 (ints)
//   wlist  : [8][LIST_CAP]   = 2048
#define S_OFF   0
#define KS_OFF  32768
#define QS_OFF  (KS_OFF + BK*KSTR)          // 50176
#define KL_OFF  (QS_OFF + BQ*KSTR)          // 51264
#define WL_OFF  (KL_OFF + 8*LIST_CAP)       // 53312
#define SMEM_FLOATS (WL_OFF + 8*LIST_CAP)   // 55360
#define SMEM_BYTES  (SMEM_FLOATS * 4)       // 221440

extern __shared__ float smem[];

__device__ __forceinline__ float warp_max(float x) {
    #pragma unroll
    for (int o = 16; o; o >>= 1) x = fmaxf(x, __shfl_xor_sync(0xffffffffu, x, o));
    return x;
}
__device__ __forceinline__ float warp_min(float x) {
    #pragma unroll
    for (int o = 16; o; o >>= 1) x = fminf(x, __shfl_xor_sync(0xffffffffu, x, o));
    return x;
}
__device__ __forceinline__ float warp_sum(float x) {
    #pragma unroll
    for (int o = 16; o; o >>= 1) x += __shfl_xor_sync(0xffffffffu, x, o);
    return x;
}

__global__ __launch_bounds__(NTHREADS, 1)
void topk_attn_kernel(const float* __restrict__ Q,
                      const float* __restrict__ K,
                      const float* __restrict__ V,
                      float* __restrict__ Out) {
    const int bh  = blockIdx.y;
    const int q0  = blockIdx.x * BQ;
    const int tid = threadIdx.x;

    float* S  = smem + S_OFF;
    float4* Ks4 = (float4*)(smem + KS_OFF);
    float4* Qs4 = (float4*)(smem + QS_OFF);
    int*   klist = (int*)(smem + KL_OFF);
    float* wlist = smem + WL_OFF;

    const size_t base = (size_t)bh * L_DIM * D_DIM;
    const float4* Q4 = (const float4*)(Q + base);
    const float4* K4 = (const float4*)(K + base);

    // ---- load Q tile (16 rows x 16 float4) ----
    {
        int r = tid >> 4, c = tid & 15;
        Qs4[r * KSTR4 + c] = Q4[(q0 + r) * 16 + c];
    }

    const int nk = q0 + BQ;                 // keys needed: 0..nk-1
    const int ntiles = (nk + BK - 1) / BK;
    const int kc = tid & 63;                // key column 0..63
    const int qr = tid >> 6;                // query row 0..3

    // ================= Phase 1: S = Q @ K^T (fp32, tiled GEMM) =================
    for (int tile = 0; tile < ntiles; tile++) {
        const int k0 = tile * BK;
        __syncthreads();   // previous tile's compute done before overwriting Ks
        #pragma unroll
        for (int i = 0; i < 16; i++) {
            int idx = i * 256 + tid;
            int r = idx >> 4, c = idx & 15;
            Ks4[r * KSTR4 + c] = K4[(k0 + r) * 16 + c];
        }
        __syncthreads();

        float acc[4][4];
        #pragma unroll
        for (int i = 0; i < 4; i++)
            #pragma unroll
            for (int j = 0; j < 4; j++) acc[i][j] = 0.f;

        #pragma unroll
        for (int d4 = 0; d4 < 16; d4++) {
            float4 qv[4], kv[4];
            #pragma unroll
            for (int i = 0; i < 4; i++) qv[i] = Qs4[(qr + 4*i) * KSTR4 + d4];
            #pragma unroll
            for (int j = 0; j < 4; j++) kv[j] = Ks4[(kc + 64*j) * KSTR4 + d4];
            #pragma unroll
            for (int i = 0; i < 4; i++)
                #pragma unroll
                for (int j = 0; j < 4; j++) {
                    acc[i][j] = fmaf(qv[i].x, kv[j].x, acc[i][j]);
                    acc[i][j] = fmaf(qv[i].y, kv[j].y, acc[i][j]);
                    acc[i][j] = fmaf(qv[i].z, kv[j].z, acc[i][j]);
                    acc[i][j] = fmaf(qv[i].w, kv[j].w, acc[i][j]);
                }
        }
        #pragma unroll
        for (int i = 0; i < 4; i++)
            #pragma unroll
            for (int j = 0; j < 4; j++)
                S[(qr + 4*i) * 2048 + k0 + kc + 64*j] = acc[i][j];
    }
    __syncthreads();

    // ================= Phase 2+3: per-warp top-k select + PV =================
    const int wid  = tid >> 5;
    const int lane = tid & 31;
    const unsigned FULL = 0xffffffffu;
    const unsigned lt = (1u << lane) - 1u;
    const float* Vb = V + base;
    float* Ob = Out + base;

    #pragma unroll 1
    for (int pass = 0; pass < 2; pass++) {
        const int qi = wid + 8 * pass;
        const int q  = q0 + qi;
        const int n  = q + 1;               // valid keys

        // load row into registers (64 per lane), track max & min of valid
        float v[64];
        float mx = -FLT_MAX, mn = FLT_MAX;
        #pragma unroll
        for (int j = 0; j < 64; j++) {
            int k = 32 * j + lane;
            float val = -FLT_MAX;
            if (k < n) {
                val = S[qi * 2048 + k];
                mn = fminf(mn, val);
            }
            v[j] = val;
            mx = fmaxf(mx, val);
        }
        mx = warp_max(mx);
        mn = warp_min(mn);

        // threshold: count(v >= t) == TOPK  (t = -FLT_MAX means "take all valid")
        float t = -FLT_MAX;
        if (n > TOPK) {
            float lo = mn, hi = mx + 1.0f;   // count(>=lo)=n>=129, count(>=hi)=0
            #pragma unroll 1
            for (int it = 0; it < 48; it++) {
                float mid = 0.5f * (lo + hi);
                if (mid <= lo || mid >= hi) break;   // converged to adjacent floats
                int c = 0;
                #pragma unroll
                for (int j = 0; j < 64; j++) c += (v[j] >= mid) ? 1 : 0;
                c = __reduce_add_sync(FULL, c);
                if (c == TOPK) { lo = mid; break; }
                if (c > TOPK) lo = mid; else hi = mid;
            }
            t = lo;   // count(>=lo) >= TOPK; == TOPK except measure-zero ties
        }

        // compact selected (k, w) into per-warp smem list, accumulate Z
        int*   kl = klist + wid * LIST_CAP;
        float* wl = wlist + wid * LIST_CAP;
        float zsum = 0.f;
        int bpos = 0;
        #pragma unroll
        for (int j = 0; j < 64; j++) {
            int k = 32 * j + lane;
            bool sel = (k < n) && (v[j] >= t);
            unsigned m = __ballot_sync(FULL, sel);
            if (sel) {
                float w = __expf(SCALE * (v[j] - mx));
                zsum += w;
                int pos = bpos + __popc(m & lt);
                if (pos < LIST_CAP) { kl[pos] = k; wl[pos] = w; }
            }
            bpos += __popc(m);
        }
        int cnt = min(bpos, LIST_CAP);
        float Z = warp_sum(zsum);
        __syncwarp();

        // gather V rows (L2-resident) and accumulate
        float a0 = 0.f, a1 = 0.f;
        int i = 0;
        #pragma unroll 1
        for (; i + 4 <= cnt; i += 4) {
            int k0_ = kl[i], k1_ = kl[i+1], k2_ = kl[i+2], k3_ = kl[i+3];
            float w0 = wl[i], w1 = wl[i+1], w2 = wl[i+2], w3 = wl[i+3];
            float x0 = Vb[k0_*64 + lane],      x1 = Vb[k1_*64 + lane];
            float x2 = Vb[k2_*64 + lane],      x3 = Vb[k3_*64 + lane];
            float y0 = Vb[k0_*64 + 32 + lane], y1 = Vb[k1_*64 + 32 + lane];
            float y2 = Vb[k2_*64 + 32 + lane], y3 = Vb[k3_*64 + 32 + lane];
            a0 = fmaf(w0, x0, a0); a0 = fmaf(w1, x1, a0);
            a0 = fmaf(w2, x2, a0); a0 = fmaf(w3, x3, a0);
            a1 = fmaf(w0, y0, a1); a1 = fmaf(w1, y1, a1);
            a1 = fmaf(w2, y2, a1); a1 = fmaf(w3, y3, a1);
        }
        #pragma unroll 1
        for (; i < cnt; i++) {
            int kk = kl[i]; float w = wl[i];
            a0 = fmaf(w, Vb[kk*64 + lane], a0);
            a1 = fmaf(w, Vb[kk*64 + 32 + lane], a1);
        }

        float inv = 1.0f / Z;
        Ob[q * 64 + lane]      = a0 * inv;
        Ob[q * 64 + 32 + lane] = a1 * inv;
    }
}

extern "C" void kernel_launch(void* const* d_in, const int* in_sizes, int n_in,
                              void* d_out, int out_size) {
    const float* Q = (const float*)d_in[0];
    const float* K = (const float*)d_in[1];
    const float* V = (const float*)d_in[2];
    float* O = (float*)d_out;

    cudaFuncSetAttribute(topk_attn_kernel,
                         cudaFuncAttributeMaxDynamicSharedMemorySize, SMEM_BYTES);
    dim3 grid(L_DIM / BQ, B_DIM * H_DIM);
    topk_attn_kernel<<<grid, NTHREADS, SMEM_BYTES>>>(Q, K, V, O);
}